// round 9
// baseline (speedup 1.0000x reference)
#include <cuda_runtime.h>
#include <cstdint>

#define N_NODES 8192
#define F_INDIM 512
#define H_DIM   256
#define D_DIM   64
#define N_EDGES 262144

// ---------------- scratch (device globals: no allocations allowed) ----------
__device__ float g_t1[N_NODES * H_DIM];
__device__ float g_h [N_NODES * H_DIM];
__device__ float g_t2[N_NODES * D_DIM];
__device__ int   g_cnt[N_NODES];
__device__ int   g_off[N_NODES + 1];
__device__ int   g_cur[N_NODES];
__device__ int   g_ccol[N_EDGES];
__device__ float g_cval[N_EDGES];

// ---------------- tf32 machinery (mma.sync only — tcgen05 is rejected by the
// harness's compute_103 virtual-arch PTX pass) ------------------------------
__device__ __forceinline__ uint32_t cvt_tf32(float f) {
    uint32_t r;
    asm("cvt.rna.tf32.f32 %0, %1;" : "=r"(r) : "f"(f));
    return r;
}
__device__ __forceinline__ void split_tf32(float a, float& hi, float& lo) {
    float hf = __uint_as_float(cvt_tf32(a));
    hi = hf;
    lo = __uint_as_float(cvt_tf32(a - hf));
}
__device__ __forceinline__ void mma8(float* c, const uint32_t* a, const uint32_t* b) {
    asm volatile(
        "mma.sync.aligned.m16n8k8.row.col.f32.tf32.tf32.f32 "
        "{%0,%1,%2,%3}, {%4,%5,%6,%7}, {%8,%9}, {%0,%1,%2,%3};"
        : "+f"(c[0]), "+f"(c[1]), "+f"(c[2]), "+f"(c[3])
        : "r"(a[0]), "r"(a[1]), "r"(a[2]), "r"(a[3]), "r"(b[0]), "r"(b[1]));
}

// ---------------- CSR build ------------------------------------------------
__global__ void k_hist(const int* __restrict__ rows) {
    int i = blockIdx.x * blockDim.x + threadIdx.x;
    if (i < N_EDGES) atomicAdd(&g_cnt[rows[i]], 1);
}
// scan also RESETS g_cnt to zero for the next call.
__global__ void k_scan() {
    __shared__ int s[1024];
    int t = threadIdx.x;
    int loc[8];
    int sum = 0;
#pragma unroll
    for (int i = 0; i < 8; i++) {
        loc[i] = g_cnt[t * 8 + i];
        g_cnt[t * 8 + i] = 0;
        sum += loc[i];
    }
    s[t] = sum;
    __syncthreads();
    for (int off = 1; off < 1024; off <<= 1) {
        int v = (t >= off) ? s[t - off] : 0;
        __syncthreads();
        s[t] += v;
        __syncthreads();
    }
    int base = (t > 0) ? s[t - 1] : 0;
#pragma unroll
    for (int i = 0; i < 8; i++) {
        g_off[t * 8 + i] = base;
        g_cur[t * 8 + i] = base;
        base += loc[i];
    }
    if (t == 1023) g_off[N_NODES] = base;
}
__global__ void k_scatter(const int* __restrict__ rows, const int* __restrict__ cols,
                          const float* __restrict__ vals) {
    int i = blockIdx.x * blockDim.x + threadIdx.x;
    if (i < N_EDGES) {
        int r = rows[i];
        int p = atomicAdd(&g_cur[r], 1);
        g_ccol[p] = cols[i];
        g_cval[p] = vals[i];
    }
}

// ---------------- SpMM -----------------------------------------------------
template <int F, int RELU>
__global__ void k_spmm(const float* __restrict__ src, float* __restrict__ dst) {
    __shared__ int   scol[F];
    __shared__ float sval[F];
    int r = blockIdx.x;
    int f = threadIdx.x;
    int s = g_off[r], e = g_off[r + 1];
    float acc = 0.0f;
    for (int base = s; base < e; base += F) {
        int n = e - base;
        if (n > F) n = F;
        if (f < n) { scol[f] = g_ccol[base + f]; sval[f] = g_cval[base + f]; }
        __syncthreads();
        for (int i = 0; i < n; i++)
            acc += sval[i] * src[scol[i] * F + f];
        __syncthreads();
    }
    dst[r * F + f] = RELU ? fmaxf(acc, 0.0f) : acc;
}

// ---------------- tf32x2 mma.sync GEMM (layers 1/2, near-fp32) --------------
template <int BM, int BN, int BK, int WM, int WN>
__global__ __launch_bounds__(256) void k_gemm_tf32x2(
    const float* __restrict__ A, const float* __restrict__ B,
    const float* __restrict__ bias, float* __restrict__ C,
    int M, int N, int K) {
    constexpr int SASTR = BK + 1;
    constexpr int SBSTR = BN + 1;
    constexpr int WNC = BN / WN;
    constexpr int MT = WM / 16;
    constexpr int NT = WN / 8;
    extern __shared__ float sm[];
    float* sAh = sm;
    float* sAl = sAh + BM * SASTR;
    float* sBh = sAl + BM * SASTR;
    float* sBl = sBh + BK * SBSTR;

    int tid = threadIdx.x, wid = tid >> 5, lane = tid & 31;
    int gid = lane >> 2, tig = lane & 3;
    int wm = (wid / WNC) * WM, wn = (wid % WNC) * WN;
    int m0 = blockIdx.y * BM, n0 = blockIdx.x * BN;

    float acc[MT][NT][4];
#pragma unroll
    for (int i = 0; i < MT; i++)
#pragma unroll
        for (int j = 0; j < NT; j++)
#pragma unroll
            for (int q = 0; q < 4; q++) acc[i][j][q] = 0.0f;

    for (int k0 = 0; k0 < K; k0 += BK) {
        for (int i = tid; i < BM * BK / 4; i += 256) {
            int r = i / (BK / 4), q = i % (BK / 4);
            float4 v = *(const float4*)&A[(size_t)(m0 + r) * K + k0 + q * 4];
            float vv[4] = {v.x, v.y, v.z, v.w};
            int base = r * SASTR + q * 4;
#pragma unroll
            for (int j = 0; j < 4; j++) {
                float hi, lo;
                split_tf32(vv[j], hi, lo);
                sAh[base + j] = hi;
                sAl[base + j] = lo;
            }
        }
        for (int i = tid; i < BK * BN / 4; i += 256) {
            int r = i / (BN / 4), q = i % (BN / 4);
            float4 v = *(const float4*)&B[(size_t)(k0 + r) * N + n0 + q * 4];
            float vv[4] = {v.x, v.y, v.z, v.w};
            int base = r * SBSTR + q * 4;
#pragma unroll
            for (int j = 0; j < 4; j++) {
                float hi, lo;
                split_tf32(vv[j], hi, lo);
                sBh[base + j] = hi;
                sBl[base + j] = lo;
            }
        }
        __syncthreads();
#pragma unroll
        for (int kc = 0; kc < BK; kc += 8) {
            uint32_t ah[MT][4], al[MT][4];
#pragma unroll
            for (int mt = 0; mt < MT; mt++) {
                int r0 = wm + mt * 16 + gid;
                ah[mt][0] = __float_as_uint(sAh[r0 * SASTR + kc + tig]);
                ah[mt][1] = __float_as_uint(sAh[(r0 + 8) * SASTR + kc + tig]);
                ah[mt][2] = __float_as_uint(sAh[r0 * SASTR + kc + tig + 4]);
                ah[mt][3] = __float_as_uint(sAh[(r0 + 8) * SASTR + kc + tig + 4]);
                al[mt][0] = __float_as_uint(sAl[r0 * SASTR + kc + tig]);
                al[mt][1] = __float_as_uint(sAl[(r0 + 8) * SASTR + kc + tig]);
                al[mt][2] = __float_as_uint(sAl[r0 * SASTR + kc + tig + 4]);
                al[mt][3] = __float_as_uint(sAl[(r0 + 8) * SASTR + kc + tig + 4]);
            }
            uint32_t bh[NT][2], bl[NT][2];
#pragma unroll
            for (int nt = 0; nt < NT; nt++) {
                int c0 = wn + nt * 8 + gid;
                bh[nt][0] = __float_as_uint(sBh[(kc + tig) * SBSTR + c0]);
                bh[nt][1] = __float_as_uint(sBh[(kc + tig + 4) * SBSTR + c0]);
                bl[nt][0] = __float_as_uint(sBl[(kc + tig) * SBSTR + c0]);
                bl[nt][1] = __float_as_uint(sBl[(kc + tig + 4) * SBSTR + c0]);
            }
#pragma unroll
            for (int mt = 0; mt < MT; mt++)
#pragma unroll
                for (int nt = 0; nt < NT; nt++) {
                    mma8(acc[mt][nt], ah[mt], bh[nt]);
                    mma8(acc[mt][nt], ah[mt], bl[nt]);
                    mma8(acc[mt][nt], al[mt], bh[nt]);
                }
        }
        __syncthreads();
    }
#pragma unroll
    for (int mt = 0; mt < MT; mt++) {
        int row0 = m0 + wm + mt * 16 + gid;
#pragma unroll
        for (int nt = 0; nt < NT; nt++) {
            int col = n0 + wn + nt * 8 + 2 * tig;
            float bx = bias[col], by = bias[col + 1];
            float2 o0 = {acc[mt][nt][0] + bx, acc[mt][nt][1] + by};
            float2 o1 = {acc[mt][nt][2] + bx, acc[mt][nt][3] + by};
            *(float2*)&C[(size_t)row0 * N + col] = o0;
            *(float2*)&C[(size_t)(row0 + 8) * N + col] = o1;
        }
    }
}

// ---------------- decode: rec = sigmoid(z z^T), symmetric tf32 mma ----------
__device__ __forceinline__ float sigmoidf_fast(float v) {
    return __fdividef(1.0f, 1.0f + __expf(-v));
}

#define ZSTR 65    // k-stride padding for z tiles
#define TSTR 132   // transpose buffer stride
#define ZZT_SMEM (128 * TSTR * 4)

__global__ __launch_bounds__(256) void k_zzt_sym(const float* __restrict__ z,
                                                 float* __restrict__ rec) {
    extern __shared__ float sm[];
    float* sA = sm;                // [128][65] rows m0..
    float* sB = sm + 128 * ZSTR;   // [128][65] rows n0..
    float* sT = sm;                // reused after compute: transpose buffer

    int tid = threadIdx.x, wid = tid >> 5, lane = tid & 31;
    int gid = lane >> 2, tig = lane & 3;
    int wm = (wid >> 2) * 64, wn = (wid & 3) * 32;

    int k = blockIdx.x, bi = 0, rem = 64;
    while (k >= rem) { k -= rem; rem--; bi++; }
    int bj = bi + k;
    int m0 = bi * 128, n0 = bj * 128;

    const float4* Z4 = (const float4*)z;
    for (int i = tid; i < 128 * 16; i += 256) {
        int r = i >> 4, q = i & 15;
        float4 va = Z4[(size_t)(m0 + r) * 16 + q];
        float4 vb = Z4[(size_t)(n0 + r) * 16 + q];
        int base = r * ZSTR + q * 4;
        sA[base + 0] = __uint_as_float(cvt_tf32(va.x));
        sA[base + 1] = __uint_as_float(cvt_tf32(va.y));
        sA[base + 2] = __uint_as_float(cvt_tf32(va.z));
        sA[base + 3] = __uint_as_float(cvt_tf32(va.w));
        sB[base + 0] = __uint_as_float(cvt_tf32(vb.x));
        sB[base + 1] = __uint_as_float(cvt_tf32(vb.y));
        sB[base + 2] = __uint_as_float(cvt_tf32(vb.z));
        sB[base + 3] = __uint_as_float(cvt_tf32(vb.w));
    }
    __syncthreads();

    float acc[4][4][4];
#pragma unroll
    for (int i = 0; i < 4; i++)
#pragma unroll
        for (int j = 0; j < 4; j++)
#pragma unroll
            for (int q = 0; q < 4; q++) acc[i][j][q] = 0.0f;

#pragma unroll
    for (int kc = 0; kc < 64; kc += 8) {
        uint32_t af[4][4];
#pragma unroll
        for (int mt = 0; mt < 4; mt++) {
            int r0 = wm + mt * 16 + gid;
            af[mt][0] = __float_as_uint(sA[r0 * ZSTR + kc + tig]);
            af[mt][1] = __float_as_uint(sA[(r0 + 8) * ZSTR + kc + tig]);
            af[mt][2] = __float_as_uint(sA[r0 * ZSTR + kc + tig + 4]);
            af[mt][3] = __float_as_uint(sA[(r0 + 8) * ZSTR + kc + tig + 4]);
        }
        uint32_t bf[4][2];
#pragma unroll
        for (int nt = 0; nt < 4; nt++) {
            int c0 = wn + nt * 8 + gid;
            bf[nt][0] = __float_as_uint(sB[c0 * ZSTR + kc + tig]);
            bf[nt][1] = __float_as_uint(sB[c0 * ZSTR + kc + tig + 4]);
        }
#pragma unroll
        for (int mt = 0; mt < 4; mt++)
#pragma unroll
            for (int nt = 0; nt < 4; nt++) mma8(acc[mt][nt], af[mt], bf[nt]);
    }

#pragma unroll
    for (int i = 0; i < 4; i++)
#pragma unroll
        for (int j = 0; j < 4; j++)
#pragma unroll
            for (int q = 0; q < 4; q++) acc[i][j][q] = sigmoidf_fast(acc[i][j][q]);

#pragma unroll
    for (int mt = 0; mt < 4; mt++) {
        int row = m0 + wm + mt * 16 + gid;
#pragma unroll
        for (int nt = 0; nt < 4; nt++) {
            int col = n0 + wn + nt * 8 + 2 * tig;
            float2 o0 = {acc[mt][nt][0], acc[mt][nt][1]};
            float2 o1 = {acc[mt][nt][2], acc[mt][nt][3]};
            *(float2*)&rec[(size_t)row * N_NODES + col] = o0;
            *(float2*)&rec[(size_t)(row + 8) * N_NODES + col] = o1;
        }
    }

    if (bi == bj) return;

    __syncthreads();
#pragma unroll
    for (int mt = 0; mt < 4; mt++) {
        int r = wm + mt * 16 + gid;
#pragma unroll
        for (int nt = 0; nt < 4; nt++) {
            int c = wn + nt * 8 + 2 * tig;
            sT[(c + 0) * TSTR + r]     = acc[mt][nt][0];
            sT[(c + 1) * TSTR + r]     = acc[mt][nt][1];
            sT[(c + 0) * TSTR + r + 8] = acc[mt][nt][2];
            sT[(c + 1) * TSTR + r + 8] = acc[mt][nt][3];
        }
    }
    __syncthreads();
#pragma unroll
    for (int it = 0; it < 16; it++) {
        int i = tid + it * 256;
        int c = i >> 5, r4 = i & 31;
        float4 v = *(float4*)&sT[c * TSTR + r4 * 4];
        *(float4*)&rec[(size_t)(n0 + c) * N_NODES + m0 + r4 * 4] = v;
    }
}

// ---------------- launch ----------------------------------------------------
extern "C" void kernel_launch(void* const* d_in, const int* in_sizes, int n_in,
                              void* d_out, int out_size) {
    const float* x    = (const float*)d_in[0];
    const int*   rows = (const int*)d_in[1];
    const int*   cols = (const int*)d_in[2];
    const float* vals = (const float*)d_in[3];
    const float* W1   = (const float*)d_in[4];
    const float* b1   = (const float*)d_in[5];
    const float* W2   = (const float*)d_in[6];
    const float* b2   = (const float*)d_in[7];

    float* z   = (float*)d_out;
    float* rec = z + (size_t)N_NODES * D_DIM;

    void *pt1 = nullptr, *ph = nullptr, *pt2 = nullptr;
    cudaGetSymbolAddress(&pt1, g_t1);
    cudaGetSymbolAddress(&ph, g_h);
    cudaGetSymbolAddress(&pt2, g_t2);

    // CSR build
    k_hist<<<N_EDGES / 256, 256>>>(rows);
    k_scan<<<1, 1024>>>();
    k_scatter<<<N_EDGES / 256, 256>>>(rows, cols, vals);

    // layer 1: BM=64,BN=64 -> grid 512 CTAs, 3+ CTAs/SM (was 128 CTAs, occ 12.5%)
    {
        constexpr int BM = 64, BN = 64, BK = 32;
        size_t smem = (size_t)(BM * (BK + 1) * 2 + BK * (BN + 1) * 2) * sizeof(float);
        cudaFuncSetAttribute(k_gemm_tf32x2<BM, BN, BK, 32, 16>,
                             cudaFuncAttributeMaxDynamicSharedMemorySize, (int)smem);
        k_gemm_tf32x2<BM, BN, BK, 32, 16>
            <<<dim3(H_DIM / BN, N_NODES / BM), 256, smem>>>(
                x, W1, b1, (float*)pt1, N_NODES, H_DIM, F_INDIM);
    }
    k_spmm<H_DIM, 1><<<N_NODES, H_DIM>>>((const float*)pt1, (float*)ph);

    // layer 2: BM=32,BN=64 -> grid 256 CTAs
    {
        constexpr int BM = 32, BN = 64, BK = 32;
        size_t smem = (size_t)(BM * (BK + 1) * 2 + BK * (BN + 1) * 2) * sizeof(float);
        cudaFuncSetAttribute(k_gemm_tf32x2<BM, BN, BK, 16, 16>,
                             cudaFuncAttributeMaxDynamicSharedMemorySize, (int)smem);
        k_gemm_tf32x2<BM, BN, BK, 16, 16>
            <<<dim3(D_DIM / BN, N_NODES / BM), 256, smem>>>(
                (const float*)ph, W2, b2, (float*)pt2, N_NODES, D_DIM, H_DIM);
    }
    k_spmm<D_DIM, 0><<<N_NODES, D_DIM>>>((const float*)pt2, z);

    // decode: symmetric upper-triangular tiles (2080 blocks)
    cudaFuncSetAttribute(k_zzt_sym, cudaFuncAttributeMaxDynamicSharedMemorySize, ZZT_SMEM);
    k_zzt_sym<<<64 * 65 / 2, 256, ZZT_SMEM>>>(z, rec);
}

// round 12
// speedup vs baseline: 1.3492x; 1.3492x over previous
#include <cuda_runtime.h>
#include <cuda_bf16.h>
#include <cstdint>

#define N_NODES 8192
#define F_INDIM 512
#define H_DIM   256
#define D_DIM   64
#define N_EDGES 262144

// ---------------- scratch (device globals: no allocations allowed) ----------
__device__ float g_t1[N_NODES * H_DIM];
__device__ float g_h [N_NODES * H_DIM];
__device__ float g_t2[N_NODES * D_DIM];
__device__ int   g_cnt[N_NODES];
__device__ int   g_off[N_NODES + 1];
__device__ int   g_cur[N_NODES];
__device__ int   g_ccol[N_EDGES];
__device__ float g_cval[N_EDGES];

// ---------------- mma machinery (mma.sync only — tcgen05 rejected by the
// harness's compute_103 virtual-arch PTX pass) ------------------------------
__device__ __forceinline__ uint32_t cvt_tf32(float f) {
    uint32_t r;
    asm("cvt.rna.tf32.f32 %0, %1;" : "=r"(r) : "f"(f));
    return r;
}
__device__ __forceinline__ void mma8(float* c, const uint32_t* a, const uint32_t* b) {
    asm volatile(
        "mma.sync.aligned.m16n8k8.row.col.f32.tf32.tf32.f32 "
        "{%0,%1,%2,%3}, {%4,%5,%6,%7}, {%8,%9}, {%0,%1,%2,%3};"
        : "+f"(c[0]), "+f"(c[1]), "+f"(c[2]), "+f"(c[3])
        : "r"(a[0]), "r"(a[1]), "r"(a[2]), "r"(a[3]), "r"(b[0]), "r"(b[1]));
}
__device__ __forceinline__ void mma16(float* c, const uint32_t* a, const uint32_t* b) {
    asm volatile(
        "mma.sync.aligned.m16n8k16.row.col.f32.bf16.bf16.f32 "
        "{%0,%1,%2,%3}, {%4,%5,%6,%7}, {%8,%9}, {%0,%1,%2,%3};"
        : "+f"(c[0]), "+f"(c[1]), "+f"(c[2]), "+f"(c[3])
        : "r"(a[0]), "r"(a[1]), "r"(a[2]), "r"(a[3]), "r"(b[0]), "r"(b[1]));
}
// split (a,b) -> packed bf16x2 hi word + lo (residual) word; low half = a
__device__ __forceinline__ void splitpack_bf16(float a, float b,
                                               uint32_t& hi, uint32_t& lo) {
    __nv_bfloat162 h = __floats2bfloat162_rn(a, b);
    float ra = a - __bfloat162float(h.x);
    float rb = b - __bfloat162float(h.y);
    __nv_bfloat162 l = __floats2bfloat162_rn(ra, rb);
    hi = *(uint32_t*)&h;
    lo = *(uint32_t*)&l;
}

// ---------------- CSR build ------------------------------------------------
__global__ void k_hist(const int* __restrict__ rows) {
    int i = blockIdx.x * blockDim.x + threadIdx.x;
    if (i < N_EDGES) atomicAdd(&g_cnt[rows[i]], 1);
}
// scan also RESETS g_cnt to zero for the next call.
__global__ void k_scan() {
    __shared__ int s[1024];
    int t = threadIdx.x;
    int loc[8];
    int sum = 0;
#pragma unroll
    for (int i = 0; i < 8; i++) {
        loc[i] = g_cnt[t * 8 + i];
        g_cnt[t * 8 + i] = 0;
        sum += loc[i];
    }
    s[t] = sum;
    __syncthreads();
    for (int off = 1; off < 1024; off <<= 1) {
        int v = (t >= off) ? s[t - off] : 0;
        __syncthreads();
        s[t] += v;
        __syncthreads();
    }
    int base = (t > 0) ? s[t - 1] : 0;
#pragma unroll
    for (int i = 0; i < 8; i++) {
        g_off[t * 8 + i] = base;
        g_cur[t * 8 + i] = base;
        base += loc[i];
    }
    if (t == 1023) g_off[N_NODES] = base;
}
__global__ void k_scatter(const int* __restrict__ rows, const int* __restrict__ cols,
                          const float* __restrict__ vals) {
    int i = blockIdx.x * blockDim.x + threadIdx.x;
    if (i < N_EDGES) {
        int r = rows[i];
        int p = atomicAdd(&g_cur[r], 1);
        g_ccol[p] = cols[i];
        g_cval[p] = vals[i];
    }
}

// ---------------- SpMM -----------------------------------------------------
template <int F, int RELU>
__global__ void k_spmm(const float* __restrict__ src, float* __restrict__ dst) {
    __shared__ int   scol[F];
    __shared__ float sval[F];
    int r = blockIdx.x;
    int f = threadIdx.x;
    int s = g_off[r], e = g_off[r + 1];
    float acc = 0.0f;
    for (int base = s; base < e; base += F) {
        int n = e - base;
        if (n > F) n = F;
        if (f < n) { scol[f] = g_ccol[base + f]; sval[f] = g_cval[base + f]; }
        __syncthreads();
        for (int i = 0; i < n; i++)
            acc += sval[i] * src[scol[i] * F + f];
        __syncthreads();
    }
    dst[r * F + f] = RELU ? fmaxf(acc, 0.0f) : acc;
}

// ---------------- bf16 3-term GEMM with bias: C = A@B + bias ----------------
// A [M,K] row-major, B [K,N] row-major. Smem holds packed bf16x2 k-pairs:
// sA*[m][kp] (kp = k/2), sB*[n][kp]. Stride KP+4 -> conflict-free fragment LDS.
// 3 MMAs per K=16: Ah*Bh + Ah*Bl + Al*Bh  (error ~2^-17, near-fp32)
template <int BM, int BN, int BK, int WM, int WN>
__global__ __launch_bounds__(256) void k_gemm_bf16x3(
    const float* __restrict__ A, const float* __restrict__ B,
    const float* __restrict__ bias, float* __restrict__ C,
    int M, int N, int K) {
    constexpr int KP = BK / 2;       // packed words per row
    constexpr int STR = KP + 4;      // conflict-free stride
    constexpr int WNC = BN / WN;
    constexpr int MT = WM / 16;
    constexpr int NT = WN / 8;
    extern __shared__ uint32_t smw[];
    uint32_t* sAh = smw;
    uint32_t* sAl = sAh + BM * STR;
    uint32_t* sBh = sAl + BM * STR;
    uint32_t* sBl = sBh + BN * STR;

    int tid = threadIdx.x, wid = tid >> 5, lane = tid & 31;
    int gid = lane >> 2, tig = lane & 3;
    int wm = (wid / WNC) * WM, wn = (wid % WNC) * WN;
    int m0 = blockIdx.y * BM, n0 = blockIdx.x * BN;

    float acc[MT][NT][4];
#pragma unroll
    for (int i = 0; i < MT; i++)
#pragma unroll
        for (int j = 0; j < NT; j++)
#pragma unroll
            for (int q = 0; q < 4; q++) acc[i][j][q] = 0.0f;

    for (int k0 = 0; k0 < K; k0 += BK) {
        // A tile: each item = one float4 (4 k) -> 2 packed words
        for (int i = tid; i < BM * (KP / 2); i += 256) {
            int r = i / (KP / 2), q = i % (KP / 2);
            float4 v = *(const float4*)&A[(size_t)(m0 + r) * K + k0 + q * 4];
            uint32_t h0, l0, h1, l1;
            splitpack_bf16(v.x, v.y, h0, l0);
            splitpack_bf16(v.z, v.w, h1, l1);
            sAh[r * STR + 2 * q]     = h0;
            sAh[r * STR + 2 * q + 1] = h1;
            sAl[r * STR + 2 * q]     = l0;
            sAl[r * STR + 2 * q + 1] = l1;
        }
        // B tile: item = (k-pair, 4 n) -> transpose to [n][kp]
        for (int i = tid; i < KP * (BN / 4); i += 256) {
            int kp = i / (BN / 4), q = i % (BN / 4);
            float4 v0 = *(const float4*)&B[(size_t)(k0 + 2 * kp) * N + n0 + q * 4];
            float4 v1 = *(const float4*)&B[(size_t)(k0 + 2 * kp + 1) * N + n0 + q * 4];
            uint32_t h, l;
            splitpack_bf16(v0.x, v1.x, h, l);
            sBh[(q * 4 + 0) * STR + kp] = h; sBl[(q * 4 + 0) * STR + kp] = l;
            splitpack_bf16(v0.y, v1.y, h, l);
            sBh[(q * 4 + 1) * STR + kp] = h; sBl[(q * 4 + 1) * STR + kp] = l;
            splitpack_bf16(v0.z, v1.z, h, l);
            sBh[(q * 4 + 2) * STR + kp] = h; sBl[(q * 4 + 2) * STR + kp] = l;
            splitpack_bf16(v0.w, v1.w, h, l);
            sBh[(q * 4 + 3) * STR + kp] = h; sBl[(q * 4 + 3) * STR + kp] = l;
        }
        __syncthreads();
#pragma unroll
        for (int kcp = 0; kcp < KP; kcp += 8) {     // K=16 per step
            uint32_t ah[MT][4], al[MT][4];
#pragma unroll
            for (int mt = 0; mt < MT; mt++) {
                int r0 = wm + mt * 16 + gid;
                ah[mt][0] = sAh[r0 * STR + kcp + tig];
                ah[mt][1] = sAh[(r0 + 8) * STR + kcp + tig];
                ah[mt][2] = sAh[r0 * STR + kcp + tig + 4];
                ah[mt][3] = sAh[(r0 + 8) * STR + kcp + tig + 4];
                al[mt][0] = sAl[r0 * STR + kcp + tig];
                al[mt][1] = sAl[(r0 + 8) * STR + kcp + tig];
                al[mt][2] = sAl[r0 * STR + kcp + tig + 4];
                al[mt][3] = sAl[(r0 + 8) * STR + kcp + tig + 4];
            }
            uint32_t bh[NT][2], bl[NT][2];
#pragma unroll
            for (int nt = 0; nt < NT; nt++) {
                int c0 = wn + nt * 8 + gid;
                bh[nt][0] = sBh[c0 * STR + kcp + tig];
                bh[nt][1] = sBh[c0 * STR + kcp + tig + 4];
                bl[nt][0] = sBl[c0 * STR + kcp + tig];
                bl[nt][1] = sBl[c0 * STR + kcp + tig + 4];
            }
#pragma unroll
            for (int mt = 0; mt < MT; mt++)
#pragma unroll
                for (int nt = 0; nt < NT; nt++) {
                    mma16(acc[mt][nt], ah[mt], bh[nt]);
                    mma16(acc[mt][nt], ah[mt], bl[nt]);
                    mma16(acc[mt][nt], al[mt], bh[nt]);
                }
        }
        __syncthreads();
    }
#pragma unroll
    for (int mt = 0; mt < MT; mt++) {
        int row0 = m0 + wm + mt * 16 + gid;
#pragma unroll
        for (int nt = 0; nt < NT; nt++) {
            int col = n0 + wn + nt * 8 + 2 * tig;
            float bx = bias[col], by = bias[col + 1];
            float2 o0 = {acc[mt][nt][0] + bx, acc[mt][nt][1] + by};
            float2 o1 = {acc[mt][nt][2] + bx, acc[mt][nt][3] + by};
            *(float2*)&C[(size_t)row0 * N + col] = o0;
            *(float2*)&C[(size_t)(row0 + 8) * N + col] = o1;
        }
    }
}

// ---------------- decode: rec = sigmoid(z z^T), symmetric tf32 mma ----------
// sigmoid via HW tanh: 1 MUFU instead of 2 (exp + rcp)
__device__ __forceinline__ float sigmoid_tanh(float v) {
    float t;
    asm("tanh.approx.f32 %0, %1;" : "=f"(t) : "f"(v * 0.5f));
    return fmaf(t, 0.5f, 0.5f);
}

#define ZSTR 65    // k-stride padding for z tiles
#define TSTR 132   // transpose buffer stride
#define ZZT_SMEM (128 * TSTR * 4)

__global__ __launch_bounds__(256) void k_zzt_sym(const float* __restrict__ z,
                                                 float* __restrict__ rec) {
    extern __shared__ float sm[];
    float* sA = sm;                // [128][65] rows m0..
    float* sB = sm + 128 * ZSTR;   // [128][65] rows n0..
    float* sT = sm;                // reused after compute: transpose buffer

    int tid = threadIdx.x, wid = tid >> 5, lane = tid & 31;
    int gid = lane >> 2, tig = lane & 3;
    int wm = (wid >> 2) * 64, wn = (wid & 3) * 32;

    int k = blockIdx.x, bi = 0, rem = 64;
    while (k >= rem) { k -= rem; rem--; bi++; }
    int bj = bi + k;
    int m0 = bi * 128, n0 = bj * 128;

    const float4* Z4 = (const float4*)z;
    for (int i = tid; i < 128 * 16; i += 256) {
        int r = i >> 4, q = i & 15;
        float4 va = Z4[(size_t)(m0 + r) * 16 + q];
        float4 vb = Z4[(size_t)(n0 + r) * 16 + q];
        int base = r * ZSTR + q * 4;
        sA[base + 0] = __uint_as_float(cvt_tf32(va.x));
        sA[base + 1] = __uint_as_float(cvt_tf32(va.y));
        sA[base + 2] = __uint_as_float(cvt_tf32(va.z));
        sA[base + 3] = __uint_as_float(cvt_tf32(va.w));
        sB[base + 0] = __uint_as_float(cvt_tf32(vb.x));
        sB[base + 1] = __uint_as_float(cvt_tf32(vb.y));
        sB[base + 2] = __uint_as_float(cvt_tf32(vb.z));
        sB[base + 3] = __uint_as_float(cvt_tf32(vb.w));
    }
    __syncthreads();

    float acc[4][4][4];
#pragma unroll
    for (int i = 0; i < 4; i++)
#pragma unroll
        for (int j = 0; j < 4; j++)
#pragma unroll
            for (int q = 0; q < 4; q++) acc[i][j][q] = 0.0f;

#pragma unroll
    for (int kc = 0; kc < 64; kc += 8) {
        uint32_t af[4][4];
#pragma unroll
        for (int mt = 0; mt < 4; mt++) {
            int r0 = wm + mt * 16 + gid;
            af[mt][0] = __float_as_uint(sA[r0 * ZSTR + kc + tig]);
            af[mt][1] = __float_as_uint(sA[(r0 + 8) * ZSTR + kc + tig]);
            af[mt][2] = __float_as_uint(sA[r0 * ZSTR + kc + tig + 4]);
            af[mt][3] = __float_as_uint(sA[(r0 + 8) * ZSTR + kc + tig + 4]);
        }
        uint32_t bf[4][2];
#pragma unroll
        for (int nt = 0; nt < 4; nt++) {
            int c0 = wn + nt * 8 + gid;
            bf[nt][0] = __float_as_uint(sB[c0 * ZSTR + kc + tig]);
            bf[nt][1] = __float_as_uint(sB[c0 * ZSTR + kc + tig + 4]);
        }
#pragma unroll
        for (int mt = 0; mt < 4; mt++)
#pragma unroll
            for (int nt = 0; nt < 4; nt++) mma8(acc[mt][nt], af[mt], bf[nt]);
    }

#pragma unroll
    for (int i = 0; i < 4; i++)
#pragma unroll
        for (int j = 0; j < 4; j++)
#pragma unroll
            for (int q = 0; q < 4; q++) acc[i][j][q] = sigmoid_tanh(acc[i][j][q]);

#pragma unroll
    for (int mt = 0; mt < 4; mt++) {
        int row = m0 + wm + mt * 16 + gid;
#pragma unroll
        for (int nt = 0; nt < 4; nt++) {
            int col = n0 + wn + nt * 8 + 2 * tig;
            float2 o0 = {acc[mt][nt][0], acc[mt][nt][1]};
            float2 o1 = {acc[mt][nt][2], acc[mt][nt][3]};
            *(float2*)&rec[(size_t)row * N_NODES + col] = o0;
            *(float2*)&rec[(size_t)(row + 8) * N_NODES + col] = o1;
        }
    }

    if (bi == bj) return;

    __syncthreads();
#pragma unroll
    for (int mt = 0; mt < 4; mt++) {
        int r = wm + mt * 16 + gid;
#pragma unroll
        for (int nt = 0; nt < 4; nt++) {
            int c = wn + nt * 8 + 2 * tig;
            sT[(c + 0) * TSTR + r]     = acc[mt][nt][0];
            sT[(c + 1) * TSTR + r]     = acc[mt][nt][1];
            sT[(c + 0) * TSTR + r + 8] = acc[mt][nt][2];
            sT[(c + 1) * TSTR + r + 8] = acc[mt][nt][3];
        }
    }
    __syncthreads();
#pragma unroll
    for (int it = 0; it < 16; it++) {
        int i = tid + it * 256;
        int c = i >> 5, r4 = i & 31;
        float4 v = *(float4*)&sT[c * TSTR + r4 * 4];
        *(float4*)&rec[(size_t)(n0 + c) * N_NODES + m0 + r4 * 4] = v;
    }
}

// ---------------- launch ----------------------------------------------------
extern "C" void kernel_launch(void* const* d_in, const int* in_sizes, int n_in,
                              void* d_out, int out_size) {
    const float* x    = (const float*)d_in[0];
    const int*   rows = (const int*)d_in[1];
    const int*   cols = (const int*)d_in[2];
    const float* vals = (const float*)d_in[3];
    const float* W1   = (const float*)d_in[4];
    const float* b1   = (const float*)d_in[5];
    const float* W2   = (const float*)d_in[6];
    const float* b2   = (const float*)d_in[7];

    float* z   = (float*)d_out;
    float* rec = z + (size_t)N_NODES * D_DIM;

    void *pt1 = nullptr, *ph = nullptr, *pt2 = nullptr;
    cudaGetSymbolAddress(&pt1, g_t1);
    cudaGetSymbolAddress(&ph, g_h);
    cudaGetSymbolAddress(&pt2, g_t2);

    // CSR build
    k_hist<<<N_EDGES / 256, 256>>>(rows);
    k_scan<<<1, 1024>>>();
    k_scatter<<<N_EDGES / 256, 256>>>(rows, cols, vals);

    // layer 1: bf16x3, BM=64 BN=128 (grid 256, warp tile 32x32)
    {
        constexpr int BM = 64, BN = 128, BK = 32;
        constexpr int STR = BK / 2 + 4;
        size_t smem = (size_t)(BM * STR + BN * STR) * 2 * sizeof(uint32_t);
        k_gemm_bf16x3<BM, BN, BK, 32, 32>
            <<<dim3(H_DIM / BN, N_NODES / BM), 256, smem>>>(
                x, W1, b1, (float*)pt1, N_NODES, H_DIM, F_INDIM);
    }
    k_spmm<H_DIM, 1><<<N_NODES, H_DIM>>>((const float*)pt1, (float*)ph);

    // layer 2: bf16x3, BM=32 BN=64 (grid 256, warp tile 16x16)
    {
        constexpr int BM = 32, BN = 64, BK = 32;
        constexpr int STR = BK / 2 + 4;
        size_t smem = (size_t)(BM * STR + BN * STR) * 2 * sizeof(uint32_t);
        k_gemm_bf16x3<BM, BN, BK, 16, 16>
            <<<dim3(D_DIM / BN, N_NODES / BM), 256, smem>>>(
                (const float*)ph, W2, b2, (float*)pt2, N_NODES, D_DIM, H_DIM);
    }
    k_spmm<D_DIM, 0><<<N_NODES, D_DIM>>>((const float*)pt2, z);

    // decode: symmetric upper-triangular tiles (2080 blocks)
    cudaFuncSetAttribute(k_zzt_sym, cudaFuncAttributeMaxDynamicSharedMemorySize, ZZT_SMEM);
    k_zzt_sym<<<64 * 65 / 2, 256, ZZT_SMEM>>>(z, rec);
}

// round 16
// speedup vs baseline: 1.5991x; 1.1853x over previous
#include <cuda_runtime.h>
#include <cuda_bf16.h>
#include <cstdint>

#define N_NODES 8192
#define F_INDIM 512
#define H_DIM   256
#define D_DIM   64
#define N_EDGES 262144

// ---------------- scratch (device globals: no allocations allowed) ----------
__device__ float g_t1[N_NODES * H_DIM];
__device__ float g_h [N_NODES * H_DIM];
__device__ float g_t2[N_NODES * D_DIM];
__device__ int   g_cnt[N_NODES];
__device__ int   g_off[N_NODES + 1];
__device__ int   g_cur[N_NODES];
__device__ int   g_ccol[N_EDGES];
__device__ float g_cval[N_EDGES];

// ---------------- mma machinery (mma.sync only — tcgen05 rejected by the
// harness's compute_103 virtual-arch PTX pass) ------------------------------
__device__ __forceinline__ void mma16(float* c, const uint32_t* a, const uint32_t* b) {
    asm volatile(
        "mma.sync.aligned.m16n8k16.row.col.f32.bf16.bf16.f32 "
        "{%0,%1,%2,%3}, {%4,%5,%6,%7}, {%8,%9}, {%0,%1,%2,%3};"
        : "+f"(c[0]), "+f"(c[1]), "+f"(c[2]), "+f"(c[3])
        : "r"(a[0]), "r"(a[1]), "r"(a[2]), "r"(a[3]), "r"(b[0]), "r"(b[1]));
}
// split (a,b) -> packed bf16x2 hi word + lo (residual) word; low half = a
__device__ __forceinline__ void splitpack_bf16(float a, float b,
                                               uint32_t& hi, uint32_t& lo) {
    __nv_bfloat162 h = __floats2bfloat162_rn(a, b);
    float ra = a - __bfloat162float(h.x);
    float rb = b - __bfloat162float(h.y);
    __nv_bfloat162 l = __floats2bfloat162_rn(ra, rb);
    hi = *(uint32_t*)&h;
    lo = *(uint32_t*)&l;
}
__device__ __forceinline__ uint32_t pack_bf16(float a, float b) {
    __nv_bfloat162 h = __floats2bfloat162_rn(a, b);
    return *(uint32_t*)&h;
}

// ---------------- CSR build ------------------------------------------------
__global__ void k_hist(const int* __restrict__ rows) {
    int i = blockIdx.x * blockDim.x + threadIdx.x;
    if (i < N_EDGES) atomicAdd(&g_cnt[rows[i]], 1);
}
// scan also RESETS g_cnt to zero for the next call.
__global__ void k_scan() {
    __shared__ int s[1024];
    int t = threadIdx.x;
    int loc[8];
    int sum = 0;
#pragma unroll
    for (int i = 0; i < 8; i++) {
        loc[i] = g_cnt[t * 8 + i];
        g_cnt[t * 8 + i] = 0;
        sum += loc[i];
    }
    s[t] = sum;
    __syncthreads();
    for (int off = 1; off < 1024; off <<= 1) {
        int v = (t >= off) ? s[t - off] : 0;
        __syncthreads();
        s[t] += v;
        __syncthreads();
    }
    int base = (t > 0) ? s[t - 1] : 0;
#pragma unroll
    for (int i = 0; i < 8; i++) {
        g_off[t * 8 + i] = base;
        g_cur[t * 8 + i] = base;
        base += loc[i];
    }
    if (t == 1023) g_off[N_NODES] = base;
}
__global__ void k_scatter(const int* __restrict__ rows, const int* __restrict__ cols,
                          const float* __restrict__ vals) {
    int i = blockIdx.x * blockDim.x + threadIdx.x;
    if (i < N_EDGES) {
        int r = rows[i];
        int p = atomicAdd(&g_cur[r], 1);
        g_ccol[p] = cols[i];
        g_cval[p] = vals[i];
    }
}

// ---------------- SpMM -----------------------------------------------------
template <int F, int RELU>
__global__ void k_spmm(const float* __restrict__ src, float* __restrict__ dst) {
    __shared__ int   scol[F];
    __shared__ float sval[F];
    int r = blockIdx.x;
    int f = threadIdx.x;
    int s = g_off[r], e = g_off[r + 1];
    float acc = 0.0f;
    for (int base = s; base < e; base += F) {
        int n = e - base;
        if (n > F) n = F;
        if (f < n) { scol[f] = g_ccol[base + f]; sval[f] = g_cval[base + f]; }
        __syncthreads();
        for (int i = 0; i < n; i++)
            acc += sval[i] * src[scol[i] * F + f];
        __syncthreads();
    }
    dst[r * F + f] = RELU ? fmaxf(acc, 0.0f) : acc;
}

// ---------------- bf16 3-term GEMM with bias: C = A@B + bias ----------------
template <int BM, int BN, int BK, int WM, int WN>
__global__ __launch_bounds__(256) void k_gemm_bf16x3(
    const float* __restrict__ A, const float* __restrict__ B,
    const float* __restrict__ bias, float* __restrict__ C,
    int M, int N, int K) {
    constexpr int KP = BK / 2;
    constexpr int STR = KP + 4;
    constexpr int WNC = BN / WN;
    constexpr int MT = WM / 16;
    constexpr int NT = WN / 8;
    extern __shared__ uint32_t smw[];
    uint32_t* sAh = smw;
    uint32_t* sAl = sAh + BM * STR;
    uint32_t* sBh = sAl + BM * STR;
    uint32_t* sBl = sBh + BN * STR;

    int tid = threadIdx.x, wid = tid >> 5, lane = tid & 31;
    int gid = lane >> 2, tig = lane & 3;
    int wm = (wid / WNC) * WM, wn = (wid % WNC) * WN;
    int m0 = blockIdx.y * BM, n0 = blockIdx.x * BN;

    float acc[MT][NT][4];
#pragma unroll
    for (int i = 0; i < MT; i++)
#pragma unroll
        for (int j = 0; j < NT; j++)
#pragma unroll
            for (int q = 0; q < 4; q++) acc[i][j][q] = 0.0f;

    for (int k0 = 0; k0 < K; k0 += BK) {
        for (int i = tid; i < BM * (KP / 2); i += 256) {
            int r = i / (KP / 2), q = i % (KP / 2);
            float4 v = *(const float4*)&A[(size_t)(m0 + r) * K + k0 + q * 4];
            uint32_t h0, l0, h1, l1;
            splitpack_bf16(v.x, v.y, h0, l0);
            splitpack_bf16(v.z, v.w, h1, l1);
            sAh[r * STR + 2 * q]     = h0;
            sAh[r * STR + 2 * q + 1] = h1;
            sAl[r * STR + 2 * q]     = l0;
            sAl[r * STR + 2 * q + 1] = l1;
        }
        for (int i = tid; i < KP * (BN / 4); i += 256) {
            int kp = i / (BN / 4), q = i % (BN / 4);
            float4 v0 = *(const float4*)&B[(size_t)(k0 + 2 * kp) * N + n0 + q * 4];
            float4 v1 = *(const float4*)&B[(size_t)(k0 + 2 * kp + 1) * N + n0 + q * 4];
            uint32_t h, l;
            splitpack_bf16(v0.x, v1.x, h, l);
            sBh[(q * 4 + 0) * STR + kp] = h; sBl[(q * 4 + 0) * STR + kp] = l;
            splitpack_bf16(v0.y, v1.y, h, l);
            sBh[(q * 4 + 1) * STR + kp] = h; sBl[(q * 4 + 1) * STR + kp] = l;
            splitpack_bf16(v0.z, v1.z, h, l);
            sBh[(q * 4 + 2) * STR + kp] = h; sBl[(q * 4 + 2) * STR + kp] = l;
            splitpack_bf16(v0.w, v1.w, h, l);
            sBh[(q * 4 + 3) * STR + kp] = h; sBl[(q * 4 + 3) * STR + kp] = l;
        }
        __syncthreads();
#pragma unroll
        for (int kcp = 0; kcp < KP; kcp += 8) {
            uint32_t ah[MT][4], al[MT][4];
#pragma unroll
            for (int mt = 0; mt < MT; mt++) {
                int r0 = wm + mt * 16 + gid;
                ah[mt][0] = sAh[r0 * STR + kcp + tig];
                ah[mt][1] = sAh[(r0 + 8) * STR + kcp + tig];
                ah[mt][2] = sAh[r0 * STR + kcp + tig + 4];
                ah[mt][3] = sAh[(r0 + 8) * STR + kcp + tig + 4];
                al[mt][0] = sAl[r0 * STR + kcp + tig];
                al[mt][1] = sAl[(r0 + 8) * STR + kcp + tig];
                al[mt][2] = sAl[r0 * STR + kcp + tig + 4];
                al[mt][3] = sAl[(r0 + 8) * STR + kcp + tig + 4];
            }
            uint32_t bh[NT][2], bl[NT][2];
#pragma unroll
            for (int nt = 0; nt < NT; nt++) {
                int c0 = wn + nt * 8 + gid;
                bh[nt][0] = sBh[c0 * STR + kcp + tig];
                bh[nt][1] = sBh[c0 * STR + kcp + tig + 4];
                bl[nt][0] = sBl[c0 * STR + kcp + tig];
                bl[nt][1] = sBl[c0 * STR + kcp + tig + 4];
            }
#pragma unroll
            for (int mt = 0; mt < MT; mt++)
#pragma unroll
                for (int nt = 0; nt < NT; nt++) {
                    mma16(acc[mt][nt], ah[mt], bh[nt]);
                    mma16(acc[mt][nt], ah[mt], bl[nt]);
                    mma16(acc[mt][nt], al[mt], bh[nt]);
                }
        }
        __syncthreads();
    }
#pragma unroll
    for (int mt = 0; mt < MT; mt++) {
        int row0 = m0 + wm + mt * 16 + gid;
#pragma unroll
        for (int nt = 0; nt < NT; nt++) {
            int col = n0 + wn + nt * 8 + 2 * tig;
            float bx = bias[col], by = bias[col + 1];
            float2 o0 = {acc[mt][nt][0] + bx, acc[mt][nt][1] + by};
            float2 o1 = {acc[mt][nt][2] + bx, acc[mt][nt][3] + by};
            *(float2*)&C[(size_t)row0 * N + col] = o0;
            *(float2*)&C[(size_t)(row0 + 8) * N + col] = o1;
        }
    }
}

// ---------------- decode: rec = sigmoid(z z^T), symmetric bf16 mma16 --------
// Single-term bf16: logit eps ~2^-9 (sigmoid-damped); measured-path evidence
// says overall rel_err stays ~2e-5, 50x under threshold.
__device__ __forceinline__ float sigmoid_tanh(float v) {
    float t;
    asm("tanh.approx.f32 %0, %1;" : "=f"(t) : "f"(v * 0.5f));
    return fmaf(t, 0.5f, 0.5f);
}

#define ZKP   32     // packed k-words per row (K=64)
#define ZSTRP 36     // packed stride (conflict-free: banks 4*gid+tig)
#define TSTR  132    // fp32 transpose buffer stride
#define ZZT_SMEM (128 * TSTR * 4)   // 67584 B; packed tiles need only 36864

__global__ __launch_bounds__(256) void k_zzt_sym(const float* __restrict__ z,
                                                 float* __restrict__ rec) {
    extern __shared__ float sm[];
    uint32_t* sA = (uint32_t*)sm;            // [128][36] packed bf16x2, rows m0..
    uint32_t* sB = sA + 128 * ZSTRP;         // [128][36] packed bf16x2, rows n0..
    float*    sT = sm;                       // reused after compute: transpose

    int tid = threadIdx.x, wid = tid >> 5, lane = tid & 31;
    int gid = lane >> 2, tig = lane & 3;
    int wm = (wid >> 2) * 64, wn = (wid & 3) * 32;

    int k = blockIdx.x, bi = 0, rem = 64;
    while (k >= rem) { k -= rem; rem--; bi++; }
    int bj = bi + k;
    int m0 = bi * 128, n0 = bj * 128;

    const float4* Z4 = (const float4*)z;
    // 128 rows x 16 float4 per tile; pack (k,k+1) pairs -> 2 words per float4
    for (int i = tid; i < 128 * 16; i += 256) {
        int r = i >> 4, q = i & 15;
        float4 va = Z4[(size_t)(m0 + r) * 16 + q];
        float4 vb = Z4[(size_t)(n0 + r) * 16 + q];
        sA[r * ZSTRP + 2 * q]     = pack_bf16(va.x, va.y);
        sA[r * ZSTRP + 2 * q + 1] = pack_bf16(va.z, va.w);
        sB[r * ZSTRP + 2 * q]     = pack_bf16(vb.x, vb.y);
        sB[r * ZSTRP + 2 * q + 1] = pack_bf16(vb.z, vb.w);
    }
    __syncthreads();

    float acc[4][4][4];
#pragma unroll
    for (int i = 0; i < 4; i++)
#pragma unroll
        for (int j = 0; j < 4; j++)
#pragma unroll
            for (int q = 0; q < 4; q++) acc[i][j][q] = 0.0f;

#pragma unroll
    for (int kcp = 0; kcp < ZKP; kcp += 8) {   // K=16 per step, 4 steps
        uint32_t af[4][4];
#pragma unroll
        for (int mt = 0; mt < 4; mt++) {
            int r0 = wm + mt * 16 + gid;
            af[mt][0] = sA[r0 * ZSTRP + kcp + tig];
            af[mt][1] = sA[(r0 + 8) * ZSTRP + kcp + tig];
            af[mt][2] = sA[r0 * ZSTRP + kcp + tig + 4];
            af[mt][3] = sA[(r0 + 8) * ZSTRP + kcp + tig + 4];
        }
        uint32_t bf[4][2];
#pragma unroll
        for (int nt = 0; nt < 4; nt++) {
            int c0 = wn + nt * 8 + gid;
            bf[nt][0] = sB[c0 * ZSTRP + kcp + tig];
            bf[nt][1] = sB[c0 * ZSTRP + kcp + tig + 4];
        }
#pragma unroll
        for (int mt = 0; mt < 4; mt++)
#pragma unroll
            for (int nt = 0; nt < 4; nt++) mma16(acc[mt][nt], af[mt], bf[nt]);
    }

#pragma unroll
    for (int i = 0; i < 4; i++)
#pragma unroll
        for (int j = 0; j < 4; j++)
#pragma unroll
            for (int q = 0; q < 4; q++) acc[i][j][q] = sigmoid_tanh(acc[i][j][q]);

#pragma unroll
    for (int mt = 0; mt < 4; mt++) {
        int row = m0 + wm + mt * 16 + gid;
#pragma unroll
        for (int nt = 0; nt < 4; nt++) {
            int col = n0 + wn + nt * 8 + 2 * tig;
            float2 o0 = {acc[mt][nt][0], acc[mt][nt][1]};
            float2 o1 = {acc[mt][nt][2], acc[mt][nt][3]};
            *(float2*)&rec[(size_t)row * N_NODES + col] = o0;
            *(float2*)&rec[(size_t)(row + 8) * N_NODES + col] = o1;
        }
    }

    if (bi == bj) return;

    __syncthreads();
#pragma unroll
    for (int mt = 0; mt < 4; mt++) {
        int r = wm + mt * 16 + gid;
#pragma unroll
        for (int nt = 0; nt < 4; nt++) {
            int c = wn + nt * 8 + 2 * tig;
            sT[(c + 0) * TSTR + r]     = acc[mt][nt][0];
            sT[(c + 1) * TSTR + r]     = acc[mt][nt][1];
            sT[(c + 0) * TSTR + r + 8] = acc[mt][nt][2];
            sT[(c + 1) * TSTR + r + 8] = acc[mt][nt][3];
        }
    }
    __syncthreads();
#pragma unroll
    for (int it = 0; it < 16; it++) {
        int i = tid + it * 256;
        int c = i >> 5, r4 = i & 31;
        float4 v = *(float4*)&sT[c * TSTR + r4 * 4];
        *(float4*)&rec[(size_t)(n0 + c) * N_NODES + m0 + r4 * 4] = v;
    }
}

// ---------------- launch ----------------------------------------------------
extern "C" void kernel_launch(void* const* d_in, const int* in_sizes, int n_in,
                              void* d_out, int out_size) {
    const float* x    = (const float*)d_in[0];
    const int*   rows = (const int*)d_in[1];
    const int*   cols = (const int*)d_in[2];
    const float* vals = (const float*)d_in[3];
    const float* W1   = (const float*)d_in[4];
    const float* b1   = (const float*)d_in[5];
    const float* W2   = (const float*)d_in[6];
    const float* b2   = (const float*)d_in[7];

    float* z   = (float*)d_out;
    float* rec = z + (size_t)N_NODES * D_DIM;

    void *pt1 = nullptr, *ph = nullptr, *pt2 = nullptr;
    cudaGetSymbolAddress(&pt1, g_t1);
    cudaGetSymbolAddress(&ph, g_h);
    cudaGetSymbolAddress(&pt2, g_t2);

    // CSR build
    k_hist<<<N_EDGES / 256, 256>>>(rows);
    k_scan<<<1, 1024>>>();
    k_scatter<<<N_EDGES / 256, 256>>>(rows, cols, vals);

    // layer 1: bf16x3, BM=64 BN=128 (grid 256, warp tile 32x32)
    {
        constexpr int BM = 64, BN = 128, BK = 32;
        constexpr int STR = BK / 2 + 4;
        size_t smem = (size_t)(BM * STR + BN * STR) * 2 * sizeof(uint32_t);
        k_gemm_bf16x3<BM, BN, BK, 32, 32>
            <<<dim3(H_DIM / BN, N_NODES / BM), 256, smem>>>(
                x, W1, b1, (float*)pt1, N_NODES, H_DIM, F_INDIM);
    }
    k_spmm<H_DIM, 1><<<N_NODES, H_DIM>>>((const float*)pt1, (float*)ph);

    // layer 2: bf16x3, BM=32 BN=64 (grid 256, warp tile 16x16)
    {
        constexpr int BM = 32, BN = 64, BK = 32;
        constexpr int STR = BK / 2 + 4;
        size_t smem = (size_t)(BM * STR + BN * STR) * 2 * sizeof(uint32_t);
        k_gemm_bf16x3<BM, BN, BK, 16, 16>
            <<<dim3(D_DIM / BN, N_NODES / BM), 256, smem>>>(
                (const float*)ph, W2, b2, (float*)pt2, N_NODES, D_DIM, H_DIM);
    }
    k_spmm<D_DIM, 0><<<N_NODES, D_DIM>>>((const float*)pt2, z);

    // decode: symmetric upper-triangular tiles (2080 blocks), bf16 mma16
    cudaFuncSetAttribute(k_zzt_sym, cudaFuncAttributeMaxDynamicSharedMemorySize, ZZT_SMEM);
    k_zzt_sym<<<64 * 65 / 2, 256, ZZT_SMEM>>>(z, rec);
}